// round 2
// baseline (speedup 1.0000x reference)
#include <cuda_runtime.h>
#include <cstdint>
#include <cstddef>

// CapsuleLayer fused kernel: u_hat GEMM (tf32x3 split mma.sync) + dynamic routing.
// One CTA per r. B=64, C=32, R=1152, IN=128, OUT=16, ITERS=3.

#define B_      64
#define C_      32
#define R_      1152
#define IN_     128
#define OUT_    16
#define STRIDE  516   // C_*OUT_ + 4 padding floats
#define SMEM_BYTES (B_ * STRIDE * 4)

// round-to-nearest fp32 -> tf32 bits
__device__ __forceinline__ unsigned f2tf(float x) {
    unsigned u;
    asm("cvt.rna.tf32.f32 %0, %1;" : "=r"(u) : "f"(x));
    return u;
}
// split v = hi + lo (both tf32), residual ~2^-22 relative
__device__ __forceinline__ void split_tf(float v, unsigned& hi, unsigned& lo) {
    hi = f2tf(v);
    lo = f2tf(v - __uint_as_float(hi));
}

// m16n8k8 tf32 MMA, D += A*B (fp32 accum)
__device__ __forceinline__ void mma8(float& d0, float& d1, float& d2, float& d3,
                                     unsigned a0, unsigned a1, unsigned a2, unsigned a3,
                                     unsigned b0, unsigned b1) {
    asm volatile(
        "mma.sync.aligned.m16n8k8.row.col.f32.tf32.tf32.f32 "
        "{%0,%1,%2,%3}, {%4,%5,%6,%7}, {%8,%9}, {%0,%1,%2,%3};"
        : "+f"(d0), "+f"(d1), "+f"(d2), "+f"(d3)
        : "r"(a0), "r"(a1), "r"(a2), "r"(a3), "r"(b0), "r"(b1));
}

extern "C" __global__ void __launch_bounds__(256, 1)
caps_fused_kernel(const float* __restrict__ X,      // (B, IN)  fp32
                  const float* __restrict__ W,      // (C, R, IN, OUT) fp32
                  float* __restrict__ out)          // (B, R, OUT) fp32
{
    extern __shared__ float uh_s[];                 // u_hat[b][c*16+o], row stride 516

    const int r     = blockIdx.x;
    const int tid   = threadIdx.x;
    const int warp  = tid >> 5;
    const int lane  = tid & 31;
    const int group = lane >> 2;   // 0..7
    const int tig   = lane & 3;    // 0..3

    // ================= Phase 1: u_hat = x @ W[:, r]  via tf32x3 MMA =================
    // GEMM per c: D[m=o(16), n=b] = A[o, i] * B[i, b],  A = W[c,r]^T view, B = x^T.
    // Warp layout: p = b-block of 16 (4 blocks), g = c-block of 16 (2 blocks).
    const int p = warp & 3;
    const int g = warp >> 2;

    // B operand (x) fragments, hi/lo split, for the two 8-b n-tiles of this warp.
    unsigned x0h[32], x0l[32], x1h[32], x1l[32];
    {
        const float* xa = X + (size_t)(16 * p + group) * IN_;
        const float* xb = X + (size_t)(16 * p + 8 + group) * IN_;
#pragma unroll
        for (int ks = 0; ks < 16; ++ks) {
            split_tf(__ldg(xa + 8 * ks + tig),     x0h[2 * ks],     x0l[2 * ks]);
            split_tf(__ldg(xa + 8 * ks + tig + 4), x0h[2 * ks + 1], x0l[2 * ks + 1]);
            split_tf(__ldg(xb + 8 * ks + tig),     x1h[2 * ks],     x1l[2 * ks]);
            split_tf(__ldg(xb + 8 * ks + tig + 4), x1h[2 * ks + 1], x1l[2 * ks + 1]);
        }
    }

#pragma unroll 1
    for (int ci = 0; ci < 16; ++ci) {
        const int c = 16 * g + ci;
        const float* Wc = W + ((size_t)c * R_ + r) * (IN_ * OUT_);
        // A fragments: a0 = W[c,r, i=8ks+tig,   o=group]
        //              a1 = W[c,r, i=8ks+tig,   o=group+8]
        //              a2 = W[c,r, i=8ks+tig+4, o=group]
        //              a3 = W[c,r, i=8ks+tig+4, o=group+8]
        float d00 = 0.f, d01 = 0.f, d02 = 0.f, d03 = 0.f;
        float d10 = 0.f, d11 = 0.f, d12 = 0.f, d13 = 0.f;
#pragma unroll
        for (int ks = 0; ks < 16; ++ks) {
            const float* q = Wc + (8 * ks + tig) * OUT_ + group;
            float a0 = __ldg(q);
            float a1 = __ldg(q + 8);
            float a2 = __ldg(q + 64);
            float a3 = __ldg(q + 72);
            unsigned a0h, a0l, a1h, a1l, a2h, a2l, a3h, a3l;
            split_tf(a0, a0h, a0l);
            split_tf(a1, a1h, a1l);
            split_tf(a2, a2h, a2l);
            split_tf(a3, a3h, a3l);
            // 3-term split, interleaved across the two independent accumulator chains
            mma8(d00, d01, d02, d03, a0h, a1h, a2h, a3h, x0h[2 * ks], x0h[2 * ks + 1]);
            mma8(d10, d11, d12, d13, a0h, a1h, a2h, a3h, x1h[2 * ks], x1h[2 * ks + 1]);
            mma8(d00, d01, d02, d03, a0l, a1l, a2l, a3l, x0h[2 * ks], x0h[2 * ks + 1]);
            mma8(d10, d11, d12, d13, a0l, a1l, a2l, a3l, x1h[2 * ks], x1h[2 * ks + 1]);
            mma8(d00, d01, d02, d03, a0h, a1h, a2h, a3h, x0l[2 * ks], x0l[2 * ks + 1]);
            mma8(d10, d11, d12, d13, a0h, a1h, a2h, a3h, x1l[2 * ks], x1l[2 * ks + 1]);
        }

        // D frag: d0=(row=group, col=2*tig) -> (o=group, b-in-tile=2*tig), etc.
        {
            const int b0 = 16 * p + 2 * tig;
            float* u0 = uh_s + (size_t)b0 * STRIDE + c * OUT_ + group;
            u0[0]          = d00;
            u0[STRIDE]     = d01;
            u0[8]          = d02;
            u0[STRIDE + 8] = d03;
            const int b1 = b0 + 8;
            float* u1 = uh_s + (size_t)b1 * STRIDE + c * OUT_ + group;
            u1[0]          = d10;
            u1[STRIDE]     = d11;
            u1[8]          = d12;
            u1[STRIDE + 8] = d13;
        }
    }
    __syncthreads();

    // ================= Phase 2: dynamic routing (3 iters), warp = 8 b's =================
    const unsigned FULL = 0xffffffffu;
#pragma unroll 1
    for (int bb = 0; bb < 8; ++bb) {
        const int b = warp * 8 + bb;
        const float* row = uh_s + (size_t)b * STRIDE;

        // lane = c view: keep u_hat[b][lane][0..15] in regs (for the b-logit update)
        float uh[16];
#pragma unroll
        for (int q4 = 0; q4 < 4; ++q4) {
            float4 v4 = *reinterpret_cast<const float4*>(row + lane * OUT_ + 4 * q4);
            uh[4 * q4 + 0] = v4.x;
            uh[4 * q4 + 1] = v4.y;
            uh[4 * q4 + 2] = v4.z;
            uh[4 * q4 + 3] = v4.w;
        }

        float blog = 0.0f;          // routing logit b[b, c=lane, r]
        const int o = lane & 15;    // lane-as-o view (halves duplicated)

#pragma unroll 1
        for (int it = 0; it < 3; ++it) {
            // softmax over c: butterfly max + sum
            float m = blog;
#pragma unroll
            for (int s = 16; s > 0; s >>= 1)
                m = fmaxf(m, __shfl_xor_sync(FULL, m, s));
            float e = __expf(blog - m);
            float Z = e;
#pragma unroll
            for (int s = 16; s > 0; s >>= 1)
                Z += __shfl_xor_sync(FULL, Z, s);
            const float cc = e / Z;

            // s[o] = sum_c cc[c] * u_hat[b][c][o]
            float sv = 0.0f;
#pragma unroll
            for (int c2 = 0; c2 < 32; ++c2)
                sv = fmaf(__shfl_sync(FULL, cc, c2), row[c2 * OUT_ + o], sv);

            // squash
            float n2 = sv * sv;
#pragma unroll
            for (int s = 8; s > 0; s >>= 1)
                n2 += __shfl_xor_sync(FULL, n2, s);
            const float nrm = sqrtf(n2);
            const float vo  = (n2 / (1.0f + n2)) * (sv / nrm);

            if (it < 2) {
                float acc = 0.0f;
#pragma unroll
                for (int o2 = 0; o2 < 16; ++o2)
                    acc = fmaf(uh[o2], __shfl_sync(FULL, vo, o2), acc);
                blog += acc;
            } else if (lane < 16) {
                out[((size_t)b * R_ + r) * OUT_ + o] = vo;
            }
        }
    }
}

extern "C" void kernel_launch(void* const* d_in, const int* in_sizes, int n_in,
                              void* d_out, int out_size) {
    (void)n_in; (void)out_size;
    const float* a = (const float*)d_in[0];
    const float* b = (const float*)d_in[1];
    const float* X = a;
    const float* W = b;
    if (in_sizes[0] != B_ * IN_) { X = b; W = a; }

    cudaFuncSetAttribute(caps_fused_kernel,
                         cudaFuncAttributeMaxDynamicSharedMemorySize, SMEM_BYTES);
    caps_fused_kernel<<<R_, 256, SMEM_BYTES>>>(X, W, (float*)d_out);
}

// round 3
// speedup vs baseline: 1.7210x; 1.7210x over previous
#include <cuda_runtime.h>
#include <cuda_fp16.h>
#include <cstdint>
#include <cstddef>

// CapsuleLayer fused kernel: u_hat GEMM (fp16x3 split, mma.sync m16n8k16) + dynamic routing.
// One CTA per r, 512 threads. B=64, C=32, R=1152, IN=128, OUT=16, ITERS=3.

#define B_      64
#define C_      32
#define R_      1152
#define IN_     128
#define OUT_    16
#define STRIDE  516   // C_*OUT_ + 4 padding floats
#define SMEM_BYTES (B_ * STRIDE * 4)
#define NTHREADS 512

__device__ __forceinline__ unsigned h2bits(half2 h) {
    return *reinterpret_cast<unsigned*>(&h);
}

// split a float pair into packed fp16 hi and fp16 lo halves (v = hi + lo, ~22 bits total)
__device__ __forceinline__ void split2(float vx, float vy, unsigned& h, unsigned& l) {
    half2 hh = __floats2half2_rn(vx, vy);
    float2 hf = __half22float2(hh);
    half2 ll = __floats2half2_rn(vx - hf.x, vy - hf.y);
    h = h2bits(hh);
    l = h2bits(ll);
}

// m16n8k16 fp16 MMA, fp32 accum: D += A*B
__device__ __forceinline__ void mma16(float& d0, float& d1, float& d2, float& d3,
                                      unsigned a0, unsigned a1, unsigned a2, unsigned a3,
                                      unsigned b0, unsigned b1) {
    asm volatile(
        "mma.sync.aligned.m16n8k16.row.col.f32.f16.f16.f32 "
        "{%0,%1,%2,%3}, {%4,%5,%6,%7}, {%8,%9}, {%0,%1,%2,%3};"
        : "+f"(d0), "+f"(d1), "+f"(d2), "+f"(d3)
        : "r"(a0), "r"(a1), "r"(a2), "r"(a3), "r"(b0), "r"(b1));
}

extern "C" __global__ void __launch_bounds__(NTHREADS, 1)
caps_fused_kernel(const float* __restrict__ X,      // (B, IN)  fp32
                  const float* __restrict__ W,      // (C, R, IN, OUT) fp32
                  float* __restrict__ out)          // (B, R, OUT) fp32
{
    extern __shared__ float uh_s[];                 // u_hat[b][c*16+o], row stride 516

    const int r     = blockIdx.x;
    const int tid   = threadIdx.x;
    const int warp  = tid >> 5;    // 0..15
    const int lane  = tid & 31;
    const int group = lane >> 2;   // 0..7
    const int tig   = lane & 3;    // 0..3

    // ========== Phase 1: u_hat = x @ W[:, r]  via fp16x3 m16n8k16 MMA ==========
    // Per c: D[m=o(16), n=b(8 per tile)] = A[o,i] * B[i,b], A = W[c,r]^T, B = x^T.
    // Warp tiling: p = b-block of 16 (2 n-tiles), g = c-block of 8.
    const int p = warp & 3;        // 0..3
    const int g = warp >> 2;       // 0..3

    // B operand (x) fragments, fp16 hi/lo, two n-tiles (b = 16p+8t+group).
    // Per kc (k16 chunk): b0 = {x[b][16kc+2tig], x[b][16kc+2tig+1]},
    //                     b1 = {x[b][16kc+2tig+8], x[b][16kc+2tig+9]}  (contiguous pairs)
    unsigned xh0[16], xl0[16], xh1[16], xl1[16];
    {
        const float2* xr0 = reinterpret_cast<const float2*>(X) + (size_t)(16 * p + group) * (IN_ / 2);
        const float2* xr1 = reinterpret_cast<const float2*>(X) + (size_t)(16 * p + 8 + group) * (IN_ / 2);
#pragma unroll
        for (int kc = 0; kc < 8; ++kc) {
            float2 v;
            v = __ldg(xr0 + 8 * kc + tig);
            split2(v.x, v.y, xh0[2 * kc], xl0[2 * kc]);
            v = __ldg(xr0 + 8 * kc + tig + 4);
            split2(v.x, v.y, xh0[2 * kc + 1], xl0[2 * kc + 1]);
            v = __ldg(xr1 + 8 * kc + tig);
            split2(v.x, v.y, xh1[2 * kc], xl1[2 * kc]);
            v = __ldg(xr1 + 8 * kc + tig + 4);
            split2(v.x, v.y, xh1[2 * kc + 1], xl1[2 * kc + 1]);
        }
    }

#pragma unroll 1
    for (int ci = 0; ci < 8; ++ci) {
        const int c = 8 * g + ci;
        const float* Wc = W + ((size_t)c * R_ + r) * (IN_ * OUT_);

        float d00 = 0.f, d01 = 0.f, d02 = 0.f, d03 = 0.f;
        float d10 = 0.f, d11 = 0.f, d12 = 0.f, d13 = 0.f;

#pragma unroll
        for (int kc = 0; kc < 8; ++kc) {
            // A fragments for this k16 chunk:
            //  a0 = {W[i][g], W[i+1][g]}       a1 = {W[i][g+8], W[i+1][g+8]}
            //  a2 = {W[i+8][g], W[i+9][g]}     a3 = {W[i+8][g+8], W[i+9][g+8]}
            //  where i = 16kc + 2tig, g = group. (W row stride = OUT_ = 16 floats)
            const float* q = Wc + (16 * kc + 2 * tig) * OUT_ + group;
            float w00 = __ldg(q);
            float w01 = __ldg(q + 16);
            float w10 = __ldg(q + 8);
            float w11 = __ldg(q + 24);
            float w20 = __ldg(q + 128);
            float w21 = __ldg(q + 144);
            float w30 = __ldg(q + 136);
            float w31 = __ldg(q + 152);

            unsigned a0h, a0l, a1h, a1l, a2h, a2l, a3h, a3l;
            split2(w00, w01, a0h, a0l);
            split2(w10, w11, a1h, a1l);
            split2(w20, w21, a2h, a2l);
            split2(w30, w31, a3h, a3l);

            // 3-term split: Wh*xh + Wl*xh + Wh*xl, interleaved over the two chains
            mma16(d00, d01, d02, d03, a0h, a1h, a2h, a3h, xh0[2 * kc], xh0[2 * kc + 1]);
            mma16(d10, d11, d12, d13, a0h, a1h, a2h, a3h, xh1[2 * kc], xh1[2 * kc + 1]);
            mma16(d00, d01, d02, d03, a0l, a1l, a2l, a3l, xh0[2 * kc], xh0[2 * kc + 1]);
            mma16(d10, d11, d12, d13, a0l, a1l, a2l, a3l, xh1[2 * kc], xh1[2 * kc + 1]);
            mma16(d00, d01, d02, d03, a0h, a1h, a2h, a3h, xl0[2 * kc], xl0[2 * kc + 1]);
            mma16(d10, d11, d12, d13, a0h, a1h, a2h, a3h, xl1[2 * kc], xl1[2 * kc + 1]);
        }

        // D frag: d0=(o=group, b=base+2tig), d1=(group, +1), d2=(group+8, +0), d3=(group+8, +1)
        {
            const int b0 = 16 * p + 2 * tig;
            float* u0 = uh_s + (size_t)b0 * STRIDE + c * OUT_ + group;
            u0[0]          = d00;
            u0[STRIDE]     = d01;
            u0[8]          = d02;
            u0[STRIDE + 8] = d03;
            const int b1 = b0 + 8;
            float* u1 = uh_s + (size_t)b1 * STRIDE + c * OUT_ + group;
            u1[0]          = d10;
            u1[STRIDE]     = d11;
            u1[8]          = d12;
            u1[STRIDE + 8] = d13;
        }
    }
    __syncthreads();

    // ========== Phase 2: dynamic routing (3 iters), warp = 4 b's ==========
    const unsigned FULL = 0xffffffffu;
#pragma unroll 1
    for (int bb = 0; bb < 4; ++bb) {
        const int b = warp * 4 + bb;
        const float* row = uh_s + (size_t)b * STRIDE;

        // lane = c view: u_hat[b][lane][0..15] in regs (for the logit update)
        float uh[16];
#pragma unroll
        for (int q4 = 0; q4 < 4; ++q4) {
            float4 v4 = *reinterpret_cast<const float4*>(row + lane * OUT_ + 4 * q4);
            uh[4 * q4 + 0] = v4.x;
            uh[4 * q4 + 1] = v4.y;
            uh[4 * q4 + 2] = v4.z;
            uh[4 * q4 + 3] = v4.w;
        }

        float blog = 0.0f;          // routing logit b[b, c=lane, r]
        const int o = lane & 15;    // lane-as-o view (halves duplicated)

#pragma unroll 1
        for (int it = 0; it < 3; ++it) {
            // softmax over c: butterfly max + sum
            float m = blog;
#pragma unroll
            for (int s = 16; s > 0; s >>= 1)
                m = fmaxf(m, __shfl_xor_sync(FULL, m, s));
            float e = __expf(blog - m);
            float Z = e;
#pragma unroll
            for (int s = 16; s > 0; s >>= 1)
                Z += __shfl_xor_sync(FULL, Z, s);
            const float cc = e / Z;

            // s[o] = sum_c cc[c] * u_hat[b][c][o]
            float sv = 0.0f;
#pragma unroll
            for (int c2 = 0; c2 < 32; ++c2)
                sv = fmaf(__shfl_sync(FULL, cc, c2), row[c2 * OUT_ + o], sv);

            // squash
            float n2 = sv * sv;
#pragma unroll
            for (int s = 8; s > 0; s >>= 1)
                n2 += __shfl_xor_sync(FULL, n2, s);
            const float nrm = sqrtf(n2);
            const float vo  = (n2 / (1.0f + n2)) * (sv / nrm);

            if (it < 2) {
                float acc = 0.0f;
#pragma unroll
                for (int o2 = 0; o2 < 16; ++o2)
                    acc = fmaf(uh[o2], __shfl_sync(FULL, vo, o2), acc);
                blog += acc;
            } else if (lane < 16) {
                out[((size_t)b * R_ + r) * OUT_ + o] = vo;
            }
        }
    }
}

extern "C" void kernel_launch(void* const* d_in, const int* in_sizes, int n_in,
                              void* d_out, int out_size) {
    (void)n_in; (void)out_size;
    const float* a = (const float*)d_in[0];
    const float* b = (const float*)d_in[1];
    const float* X = a;
    const float* W = b;
    if (in_sizes[0] != B_ * IN_) { X = b; W = a; }

    cudaFuncSetAttribute(caps_fused_kernel,
                         cudaFuncAttributeMaxDynamicSharedMemorySize, SMEM_BYTES);
    caps_fused_kernel<<<R_, NTHREADS, SMEM_BYTES>>>(X, W, (float*)d_out);
}

// round 5
// speedup vs baseline: 2.0598x; 1.1969x over previous
#include <cuda_runtime.h>
#include <cuda_fp16.h>
#include <cstdint>
#include <cstddef>

// CapsuleLayer fused: u_hat GEMM (fp16x3, mma.sync m16n8k16, SMEM-staged W via
// ldmatrix.trans) + dynamic routing. One CTA per r, 512 threads.
// B=64, C=32, R=1152, IN=128, OUT=16, ITERS=3.

#define B_      64
#define C_      32
#define R_      1152
#define IN_     128
#define OUT_    16
#define STRIDE  516                       // C_*OUT_ + 4 pad floats (u_hat rows)
#define UH_BYTES (B_ * STRIDE * 4)        // 132096
#define ROWH    24                        // halfs per W-smem row (16 data + 8 pad = 48B, 16-aligned)
#define ROWB    (ROWH * 2)                // 48 bytes
#define WTILE_B (IN_ * ROWB)              // one (c, hi|lo) tile: 128*48 = 6144 B
#define SMEM_BYTES (UH_BYTES + 8 * WTILE_B)   // 2 bufs x 2 c x 2 (hi/lo) = +49152
#define NTHREADS 512

__device__ __forceinline__ unsigned h2bits(half2 h) {
    return *reinterpret_cast<unsigned*>(&h);
}
// v = hi + lo with hi,lo fp16 (packed pairs); ~22 effective bits
__device__ __forceinline__ void split2(float vx, float vy, unsigned& h, unsigned& l) {
    half2 hh = __floats2half2_rn(vx, vy);
    float2 hf = __half22float2(hh);
    half2 ll = __floats2half2_rn(vx - hf.x, vy - hf.y);
    h = h2bits(hh);
    l = h2bits(ll);
}

__device__ __forceinline__ void mma16(float& d0, float& d1, float& d2, float& d3,
                                      unsigned a0, unsigned a1, unsigned a2, unsigned a3,
                                      unsigned b0, unsigned b1) {
    asm volatile(
        "mma.sync.aligned.m16n8k16.row.col.f32.f16.f16.f32 "
        "{%0,%1,%2,%3}, {%4,%5,%6,%7}, {%8,%9}, {%0,%1,%2,%3};"
        : "+f"(d0), "+f"(d1), "+f"(d2), "+f"(d3)
        : "r"(a0), "r"(a1), "r"(a2), "r"(a3), "r"(b0), "r"(b1));
}

__device__ __forceinline__ void ldsm4t(unsigned& r0, unsigned& r1, unsigned& r2, unsigned& r3,
                                       unsigned addr) {
    asm volatile("ldmatrix.sync.aligned.m8n8.x4.trans.shared.b16 {%0,%1,%2,%3}, [%4];"
                 : "=r"(r0), "=r"(r1), "=r"(r2), "=r"(r3) : "r"(addr));
}

extern "C" __global__ void __launch_bounds__(NTHREADS, 1)
caps_fused_kernel(const float* __restrict__ X,      // (B, IN)  fp32
                  const float* __restrict__ W,      // (C, R, IN, OUT) fp32
                  float* __restrict__ out)          // (B, R, OUT) fp32
{
    extern __shared__ float uh_s[];                 // u_hat[b][c*16+o], stride 516
    char* wbuf = reinterpret_cast<char*>(uh_s) + UH_BYTES;

    const int r     = blockIdx.x;
    const int tid   = threadIdx.x;
    const int warp  = tid >> 5;    // 0..15
    const int lane  = tid & 31;
    const int group = lane >> 2;   // 0..7
    const int tig   = lane & 3;    // 0..3

    // ===== Phase 1: u_hat = x @ W[:, r] (fp16x3), W staged through SMEM =====
    // Warp tiling per c-pair: cc = warp>>3 selects c of the pair, p = warp&7 is
    // the n-tile (b = 8p..8p+7). Two accumulator chains (even/odd kc).
    const int cc = warp >> 3;      // 0/1
    const int p  = warp & 7;       // 0..7

    // B operand (x) fragments, fp16 hi/lo: b = 8p + group (n-col = group).
    unsigned xh[16], xl[16];
    {
        const float2* xr = reinterpret_cast<const float2*>(X) + (size_t)(8 * p + group) * (IN_ / 2);
#pragma unroll
        for (int kc = 0; kc < 8; ++kc) {
            float2 v;
            v = __ldg(xr + 8 * kc + tig);
            split2(v.x, v.y, xh[2 * kc], xl[2 * kc]);
            v = __ldg(xr + 8 * kc + tig + 4);
            split2(v.x, v.y, xh[2 * kc + 1], xl[2 * kc + 1]);
        }
    }

    // Staging role: per c-pair this thread stores one float4 per c:
    //   i = tid/4  (0..127), o4 = (tid%4)*4.
    const int st_i  = tid >> 2;
    const int st_o4 = (tid & 3) << 2;
    const float* Wr = W + (size_t)r * (IN_ * OUT_);              // + c*R*2048
    const size_t cstride = (size_t)R_ * (IN_ * OUT_);

    // ldmatrix source (within a (c,hi/lo) tile):
    //   mat0: lanes 0-7   -> rows i=0..7,  col 0   (a0: o0-7,  k0-7)
    //   mat1: lanes 8-15  -> rows i=0..7,  col 8   (a1: o8-15, k0-7)
    //   mat2: lanes 16-23 -> rows i=8..15, col 0   (a2: o0-7,  k8-15)
    //   mat3: lanes 24-31 -> rows i=8..15, col 8   (a3: o8-15, k8-15)
    const int lm_i = (lane & 7) + ((lane >> 4) << 3);
    const int lm_byte = lm_i * ROWB + ((lane & 8) ? 16 : 0);     // multiples of 16
    const unsigned wbuf_s = (unsigned)__cvta_generic_to_shared(wbuf);

    // prefetch c-pair 0
    float4 vA0 = __ldg(reinterpret_cast<const float4*>(Wr + (size_t)0 * cstride + st_i * OUT_ + st_o4));
    float4 vA1 = __ldg(reinterpret_cast<const float4*>(Wr + (size_t)1 * cstride + st_i * OUT_ + st_o4));

#pragma unroll 1
    for (int pi = 0; pi < 16; ++pi) {
        const int buf = pi & 1;
        // ---- split + store both c's of this pair into wbuf[buf] ----
        {
            char* base0 = wbuf + (size_t)(buf * 4 + 0) * WTILE_B;   // c even: hi
            char* base1 = wbuf + (size_t)(buf * 4 + 1) * WTILE_B;   //         lo
            char* base2 = wbuf + (size_t)(buf * 4 + 2) * WTILE_B;   // c odd:  hi
            char* base3 = wbuf + (size_t)(buf * 4 + 3) * WTILE_B;   //         lo
            const int boff = st_i * ROWB + st_o4 * 2;
            unsigned h01, l01, h23, l23;
            split2(vA0.x, vA0.y, h01, l01);
            split2(vA0.z, vA0.w, h23, l23);
            *reinterpret_cast<uint2*>(base0 + boff) = make_uint2(h01, h23);
            *reinterpret_cast<uint2*>(base1 + boff) = make_uint2(l01, l23);
            split2(vA1.x, vA1.y, h01, l01);
            split2(vA1.z, vA1.w, h23, l23);
            *reinterpret_cast<uint2*>(base2 + boff) = make_uint2(h01, h23);
            *reinterpret_cast<uint2*>(base3 + boff) = make_uint2(l01, l23);
        }
        // ---- prefetch next pair (latency hidden behind sync + MMA) ----
        if (pi < 15) {
            vA0 = __ldg(reinterpret_cast<const float4*>(Wr + (size_t)(2 * pi + 2) * cstride + st_i * OUT_ + st_o4));
            vA1 = __ldg(reinterpret_cast<const float4*>(Wr + (size_t)(2 * pi + 3) * cstride + st_i * OUT_ + st_o4));
        }
        __syncthreads();

        // ---- MMA for c = 2*pi + cc ----
        const unsigned hbase = wbuf_s + (unsigned)(buf * 4 + cc * 2) * WTILE_B + lm_byte;
        const unsigned lbase = hbase + WTILE_B;

        float d0 = 0.f, d1 = 0.f, d2 = 0.f, d3 = 0.f;   // chain A (even kc)
        float e0 = 0.f, e1 = 0.f, e2 = 0.f, e3 = 0.f;   // chain B (odd kc)
#pragma unroll
        for (int kc = 0; kc < 8; kc += 2) {
            unsigned ah0, ah1, ah2, ah3, al0, al1, al2, al3;
            unsigned bh0, bh1, bh2, bh3, bl0, bl1, bl2, bl3;
            ldsm4t(ah0, ah1, ah2, ah3, hbase + (unsigned)(16 * kc) * ROWB);
            ldsm4t(al0, al1, al2, al3, lbase + (unsigned)(16 * kc) * ROWB);
            ldsm4t(bh0, bh1, bh2, bh3, hbase + (unsigned)(16 * kc + 16) * ROWB);
            ldsm4t(bl0, bl1, bl2, bl3, lbase + (unsigned)(16 * kc + 16) * ROWB);
            // 3-term fp16 split per kc, interleaved across the two chains
            mma16(d0, d1, d2, d3, ah0, ah1, ah2, ah3, xh[2 * kc],     xh[2 * kc + 1]);
            mma16(e0, e1, e2, e3, bh0, bh1, bh2, bh3, xh[2 * kc + 2], xh[2 * kc + 3]);
            mma16(d0, d1, d2, d3, al0, al1, al2, al3, xh[2 * kc],     xh[2 * kc + 1]);
            mma16(e0, e1, e2, e3, bl0, bl1, bl2, bl3, xh[2 * kc + 2], xh[2 * kc + 3]);
            mma16(d0, d1, d2, d3, ah0, ah1, ah2, ah3, xl[2 * kc],     xl[2 * kc + 1]);
            mma16(e0, e1, e2, e3, bh0, bh1, bh2, bh3, xl[2 * kc + 2], xl[2 * kc + 3]);
        }
        d0 += e0; d1 += e1; d2 += e2; d3 += e3;

        // D frag -> uh_s:  d0=(o=group, b=8p+2tig), d1=(group, +1),
        //                  d2=(group+8, +0), d3=(group+8, +1)
        {
            const int c  = 2 * pi + cc;
            const int b0 = 8 * p + 2 * tig;
            float* u0 = uh_s + (size_t)b0 * STRIDE + c * OUT_ + group;
            u0[0]          = d0;
            u0[STRIDE]     = d1;
            u0[8]          = d2;
            u0[STRIDE + 8] = d3;
        }
        __syncthreads();   // wbuf[buf] fully consumed before refill at pi+2
    }

    // ========== Phase 2: dynamic routing (3 iters), warp = 4 b's ==========
    const unsigned FULL = 0xffffffffu;
#pragma unroll 1
    for (int bb = 0; bb < 4; ++bb) {
        const int b = warp * 4 + bb;
        const float* row = uh_s + (size_t)b * STRIDE;

        float uh[16];   // lane = c view of u_hat[b][lane][:]
#pragma unroll
        for (int q4 = 0; q4 < 4; ++q4) {
            float4 v4 = *reinterpret_cast<const float4*>(row + lane * OUT_ + 4 * q4);
            uh[4 * q4 + 0] = v4.x;
            uh[4 * q4 + 1] = v4.y;
            uh[4 * q4 + 2] = v4.z;
            uh[4 * q4 + 3] = v4.w;
        }

        float blog = 0.0f;
        const int o = lane & 15;

#pragma unroll 1
        for (int it = 0; it < 3; ++it) {
            float m = blog;
#pragma unroll
            for (int s = 16; s > 0; s >>= 1)
                m = fmaxf(m, __shfl_xor_sync(FULL, m, s));
            float e = __expf(blog - m);
            float Z = e;
#pragma unroll
            for (int s = 16; s > 0; s >>= 1)
                Z += __shfl_xor_sync(FULL, Z, s);
            const float ccf = e / Z;

            float sv = 0.0f;
#pragma unroll
            for (int c2 = 0; c2 < 32; ++c2)
                sv = fmaf(__shfl_sync(FULL, ccf, c2), row[c2 * OUT_ + o], sv);

            float n2 = sv * sv;
#pragma unroll
            for (int s = 8; s > 0; s >>= 1)
                n2 += __shfl_xor_sync(FULL, n2, s);
            const float nrm = sqrtf(n2);
            const float vo  = (n2 / (1.0f + n2)) * (sv / nrm);

            if (it < 2) {
                float acc = 0.0f;
#pragma unroll
                for (int o2 = 0; o2 < 16; ++o2)
                    acc = fmaf(uh[o2], __shfl_sync(FULL, vo, o2), acc);
                blog += acc;
            } else if (lane < 16) {
                out[((size_t)b * R_ + r) * OUT_ + o] = vo;
            }
        }
    }
}

extern "C" void kernel_launch(void* const* d_in, const int* in_sizes, int n_in,
                              void* d_out, int out_size) {
    (void)n_in; (void)out_size;
    const float* a = (const float*)d_in[0];
    const float* b = (const float*)d_in[1];
    const float* X = a;
    const float* W = b;
    if (in_sizes[0] != B_ * IN_) { X = b; W = a; }

    cudaFuncSetAttribute(caps_fused_kernel,
                         cudaFuncAttributeMaxDynamicSharedMemorySize, SMEM_BYTES);
    caps_fused_kernel<<<R_, NTHREADS, SMEM_BYTES>>>(X, W, (float*)d_out);
}